// round 14
// baseline (speedup 1.0000x reference)
#include <cuda_runtime.h>
#include <cuda_bf16.h>

// Shapes fixed by the problem definition.
#define BATCH    256
#define HWPIX    1024           // 32*32
#define CHAN     256
#define NPART    4
#define PSIZE    64             // BATCH / NPART
#define EPSV     0.001f
#define UNIT_PIX 64
#define SUNITS   1024u          // units per partition (64 batches * 16 chunks)
#define TOTS     4096u          // total stats units
#define CPS      4              // CTAs per SM (64 regs, high MLP -- proven)
#define W_NORM   0x2000u        // work-item flag: normalize
#define W_RETRY  0xFFFFFFFEu
#define W_DONE   0xFFFFFFFFu

// Scratch (allocation-free rule): device globals. Everything is reset by the
// last-finishing CTA before the kernel retires -> every graph replay sees
// identical initial state.
__device__ float    g_sum[NPART][CHAN];
__device__ float    g_sq [NPART][CHAN];
__device__ unsigned g_tks;            // stats ticket (partition-major order)
__device__ unsigned g_ntk[NPART];     // per-partition norm tickets
__device__ unsigned g_pdone[NPART];   // per-partition completed stats units
__device__ unsigned g_done;           // exit handshake

// Non-blocking work picker (t0 only). Preference: normalize the lowest fully-
// statted partition (its x is freshest in L2); else a stats unit; else RETRY
// while norm work is pending, DONE when everything is consumed.
__device__ __forceinline__ unsigned pick_try() {
    #pragma unroll
    for (int p = 0; p < NPART; p++) {
        if (__ldcg(&g_pdone[p]) >= SUNITS && __ldcg(&g_ntk[p]) < SUNITS) {
            unsigned j = atomicAdd(&g_ntk[p], 1u);
            if (j < SUNITS) return W_NORM | ((unsigned)p << 10) | j;
        }
    }
    if (__ldcg(&g_tks) < TOTS) {
        unsigned u = atomicAdd(&g_tks, 1u);
        if (u < TOTS) return u;
    }
    bool pending = false;
    #pragma unroll
    for (int p = 0; p < NPART; p++)
        if (__ldcg(&g_ntk[p]) < SUNITS) pending = true;
    return pending ? W_RETRY : W_DONE;
}

// ---------------------------------------------------------------------------
// One persistent kernel, ONE work loop: stats units (partition-major) and
// norm units (per-partition, released when that partition's stats complete,
// consumed in REVERSE order = newest x first). No global barrier: each of
// the 4 partition boundaries gets its own L2 reuse window (~64 MB = window).
// grid = CPS*num_SMs, all CTAs resident -> gating spins are deadlock-free
// (blocking re-pick only happens with no unflushed unit on this CTA).
// ---------------------------------------------------------------------------
__global__ void __launch_bounds__(256, CPS)
k_fused(const float4* __restrict__ x, float4* __restrict__ out,
        const float* __restrict__ gamma, const float* __restrict__ beta,
        const int* __restrict__ perm) {
    const int      t    = threadIdx.x;
    const int      c4   = t & 63;
    const int      psub = t >> 6;
    const unsigned nCTA = gridDim.x;

    __shared__ int      sbatch[BATCH];   // flat: partition p -> rows [64p,64p+64)
    __shared__ float    ssum[4][CHAN];   // reduction arrays (post-adds sync guards)
    __shared__ float    ssq [4][CHAN];
    __shared__ float    sscale[NPART][CHAN];
    __shared__ float    sbias [NPART][CHAN];
    __shared__ unsigned stk[2];          // double-buffered work broadcast
    __shared__ int      s_curp;          // partition whose fold is cached
    __shared__ int      slast;

    sbatch[t] = perm[t];                 // partition p's batches = perm[64p..]
    if (t == 0) { s_curp = -1; stk[0] = pick_try(); }
    __syncthreads();

    for (unsigned it = 0; ; it++) {
        unsigned w = stk[it & 1u];
        if (w == W_RETRY) {              // nothing was ready at prefetch time:
            if (t == 0) {                // safe to block now (no unflushed unit)
                unsigned r;
                while ((r = pick_try()) == W_RETRY) { __nanosleep(256); }
                stk[it & 1u] = r;
            }
            __syncthreads();
            w = stk[it & 1u];
        }
        if (w == W_DONE) break;
        if (t == 0) stk[(it + 1u) & 1u] = pick_try();   // non-blocking prefetch

        if (!(w & W_NORM)) {
            // ---------------- stats unit: w = p*1024 + i -----------------
            const int p     = (int)(w >> 10);
            const int b     = sbatch[w >> 4];        // p*64 + (i>>4)
            const int chunk = (int)(w & 15u);
            const float4* base =
                x + ((size_t)b * HWPIX + (size_t)chunk * UNIT_PIX) * (CHAN / 4) + c4;

            float4 s = make_float4(0.f, 0.f, 0.f, 0.f);
            float4 q = make_float4(0.f, 0.f, 0.f, 0.f);
            #pragma unroll
            for (int i = 0; i < 16; i++) {
                float4 v = base[(size_t)(i * 4 + psub) * (CHAN / 4)];
                s.x += v.x; s.y += v.y; s.z += v.z; s.w += v.w;
                q.x += v.x * v.x; q.y += v.y * v.y; q.z += v.z * v.z; q.w += v.w * v.w;
            }

            const int cbase = c4 * 4;
            ssum[psub][cbase + 0] = s.x; ssum[psub][cbase + 1] = s.y;
            ssum[psub][cbase + 2] = s.z; ssum[psub][cbase + 3] = s.w;
            ssq[psub][cbase + 0]  = q.x; ssq[psub][cbase + 1]  = q.y;
            ssq[psub][cbase + 2]  = q.z; ssq[psub][cbase + 3]  = q.w;
            __syncthreads();             // reduce ready + publish prefetch

            atomicAdd(&g_sum[p][t], ssum[0][t] + ssum[1][t] + ssum[2][t] + ssum[3][t]);
            atomicAdd(&g_sq[p][t],  ssq[0][t]  + ssq[1][t]  + ssq[2][t]  + ssq[3][t]);
            __syncthreads();             // all adds issued + smem reads done
            if (t == 0) {                // release this unit (same pattern as
                __threadfence();         //  the R5-R13 grid barrier)
                atomicAdd(&g_pdone[p], 1u);
            }
        } else {
            // ------------- norm unit: reverse order within partition ------
            const int p      = (int)((w >> 10) & 3u);
            const unsigned i = (SUNITS - 1u) - (w & 1023u);  // newest first
            const int b      = sbatch[(p << 6) | (int)(i >> 4)];
            const int chunk  = (int)(i & 15u);

            if (s_curp != p) {           // fold this partition's stats once
                __threadfence();         // acquire vs pdone release
                const float invN = 1.0f / (float)(PSIZE * HWPIX);
                float4 sm = __ldcg((const float4*)&g_sum[p][c4 * 4]);
                float4 sq = __ldcg((const float4*)&g_sq[p][c4 * 4]);
                float4 ga = *(const float4*)&gamma[p * CHAN + c4 * 4];
                float4 be = *(const float4*)&beta[p * CHAN + c4 * 4];
                float mx = sm.x * invN, my = sm.y * invN,
                      mz = sm.z * invN, mw = sm.w * invN;
                float scx = ga.x * rsqrtf(sq.x * invN - mx * mx + EPSV);
                float scy = ga.y * rsqrtf(sq.y * invN - my * my + EPSV);
                float scz = ga.z * rsqrtf(sq.z * invN - mz * mz + EPSV);
                float scw = ga.w * rsqrtf(sq.w * invN - mw * mw + EPSV);
                // 4 threads per quad write identical values: benign
                *(float4*)&sscale[p][c4 * 4] =
                    make_float4(scx, scy, scz, scw);
                *(float4*)&sbias[p][c4 * 4] =
                    make_float4(be.x - mx * scx, be.y - my * scy,
                                be.z - mz * scz, be.w - mw * scw);
                __syncthreads();
                if (t == 0) s_curp = p;
            }

            const float4 sc = *(const float4*)&sscale[p][c4 * 4];
            const float4 bi = *(const float4*)&sbias[p][c4 * 4];

            const size_t base =
                ((size_t)b * HWPIX + (size_t)chunk * UNIT_PIX) * (CHAN / 4) + c4;
            #pragma unroll
            for (int i2 = 0; i2 < 16; i2++) {
                size_t idx = base + (size_t)(i2 * 4 + psub) * (CHAN / 4);
                float4 v = x[idx];
                v.x = v.x * sc.x + bi.x;
                v.y = v.y * sc.y + bi.y;
                v.z = v.z * sc.z + bi.z;
                v.w = v.w * sc.w + bi.w;
                out[idx] = v;
            }
            __syncthreads();             // publish prefetched work + s_curp
        }
    }

    // ------------- Exit handshake: last CTA resets ALL state --------------
    __syncthreads();
    if (t == 0) slast = (atomicAdd(&g_done, 1u) == nCTA - 1u) ? 1 : 0;
    __syncthreads();
    if (slast) {
        float* gs = &g_sum[0][0];
        float* gq = &g_sq[0][0];
        #pragma unroll
        for (int i = t; i < NPART * CHAN; i += 256) { gs[i] = 0.f; gq[i] = 0.f; }
        if (t < NPART) { g_ntk[t] = 0u; g_pdone[t] = 0u; }
        if (t == 0) g_tks = 0u;
        __threadfence();
        __syncthreads();
        if (t == 0) atomicExch(&g_done, 0u);
    }
}

// ---------------------------------------------------------------------------
extern "C" void kernel_launch(void* const* d_in, const int* in_sizes, int n_in,
                              void* d_out, int out_size) {
    const float* x     = (const float*)d_in[0];
    const float* gamma = (const float*)d_in[1];
    const float* beta  = (const float*)d_in[2];
    const int*   perm  = (const int*)d_in[3];

    int nsm = 0;
    cudaDeviceGetAttribute(&nsm, cudaDevAttrMultiProcessorCount, 0);
    if (nsm <= 0) nsm = 148;                 // defensive fallback
    const int grid = CPS * nsm;              // __launch_bounds__ => all resident

    k_fused<<<grid, 256>>>((const float4*)x, (float4*)d_out, gamma, beta, perm);
}